// round 8
// baseline (speedup 1.0000x reference)
#include <cuda_runtime.h>
#include <cuda_bf16.h>

#define MAXN 100000
#define MAXE 3200000
#define NGRAPH 512
#define DMAX 64

// -------- device scratch --------
__device__ int   g_degcnt[MAXN];
__device__ int   g_rs    [MAXN];
__device__ int   g_cursor[MAXN];
__device__ int   g_bsum  [512];
__device__ int   g_boff  [512];
__device__ int   g_csrc  [MAXE];
__device__ float g_dis   [MAXN];
__device__ float g_hp    [MAXN * DMAX];
__device__ float g_out   [MAXN * DMAX];
__device__ float g_pool  [NGRAPH * DMAX];
__device__ float g_cnt   [NGRAPH];

// -------- degree --------
__global__ void deg_kernel(const int* __restrict__ dst, int E) {
    int i = blockIdx.x * blockDim.x + threadIdx.x;
    if (i < E) atomicAdd(&g_degcnt[__ldg(&dst[i])], 1);
}

// -------- dis = rsqrt(deg+1) --------
__global__ void dis_kernel(int N) {
    int i = blockIdx.x * blockDim.x + threadIdx.x;
    if (i < N) g_dis[i] = rsqrtf((float)g_degcnt[i] + 1.0f);
}

// -------- exclusive scan of degcnt --------
__global__ void scan1_kernel(int N) {
    __shared__ int s[512];
    int t = threadIdx.x;
    int i = blockIdx.x * 512 + t;
    int v = (i < N) ? g_degcnt[i] : 0;
    s[t] = v; __syncthreads();
    for (int o = 1; o < 512; o <<= 1) {
        int u = (t >= o) ? s[t - o] : 0;
        __syncthreads(); s[t] += u; __syncthreads();
    }
    if (i < N) g_rs[i] = s[t] - v;
    if (t == 511) g_bsum[blockIdx.x] = s[511];
}
__global__ void scan2_kernel(int nb) {
    __shared__ int s[512];
    int t = threadIdx.x;
    int v = (t < nb) ? g_bsum[t] : 0;
    s[t] = v; __syncthreads();
    for (int o = 1; o < 512; o <<= 1) {
        int u = (t >= o) ? s[t - o] : 0;
        __syncthreads(); s[t] += u; __syncthreads();
    }
    if (t < nb) g_boff[t] = s[t] - v;
}
__global__ void scan3_kernel(int N) {
    int i = blockIdx.x * blockDim.x + threadIdx.x;
    if (i < N) {
        int r = g_rs[i] + g_boff[i >> 9];
        g_rs[i] = r;
        g_cursor[i] = r;
    }
}

// -------- CSR fill --------
__global__ void fill_csr_kernel(const int* __restrict__ src,
                                const int* __restrict__ dst, int E) {
    int i = blockIdx.x * blockDim.x + threadIdx.x;
    if (i < E) {
        int d = __ldg(&dst[i]);
        int p = atomicAdd(&g_cursor[d], 1);
        g_csrc[p] = __ldg(&src[i]);
    }
}

// -------- GEMM + pre-scale by dis: hp = (X@W) * dis (fp32) --------
template<int K, int M, int R>
__global__ void gemm_kernel(const float* __restrict__ Xext, int xsel,
                            const float* __restrict__ W, int N) {
    constexpr int G = M / 4;
    __shared__ float4 sw[K * G];
    __shared__ float  sx[R * (K + 1)];
    const float* __restrict__ X = xsel ? g_out : Xext;
    int tid = threadIdx.x;
    const float4* W4 = (const float4*)W;
    for (int i = tid; i < K * G; i += blockDim.x) sw[i] = W4[i];
    int row0 = blockIdx.x * R;
    int nrows = N - row0; if (nrows > R) nrows = R;
    if (nrows <= 0) return;
    for (int i = tid; i < nrows * K; i += blockDim.x) {
        int r = i / K, k = i - r * K;
        sx[r * (K + 1) + k] = X[(size_t)(row0 + r) * K + k];
    }
    __syncthreads();
    int r = tid / G, g = tid - r * G;
    if (r < nrows) {
        float4 acc = {0.f, 0.f, 0.f, 0.f};
        const float* xr = &sx[r * (K + 1)];
        #pragma unroll 8
        for (int k = 0; k < K; k++) {
            float xv = xr[k];
            float4 wv = sw[k * G + g];
            acc.x += xv * wv.x; acc.y += xv * wv.y;
            acc.z += xv * wv.z; acc.w += xv * wv.w;
        }
        float ds = g_dis[row0 + r];
        acc.x *= ds; acc.y *= ds; acc.z *= ds; acc.w *= ds;
        ((float4*)g_hp)[(size_t)(row0 + r) * G + g] = acc;
    }
}

// -------- gather + finalize: out = relu(dis * (sum hp[src] + hp[self]) + b) --------
// float2 row layout, W = D/2 active lanes; explicit 8-deep load batching.
template<int D>
__global__ void __launch_bounds__(256)
gather_kernel(const float* __restrict__ bias, int N) {
    constexpr int W = D / 2;
    int v = (int)((blockIdx.x * blockDim.x + threadIdx.x) >> 5);
    int lane = threadIdx.x & 31;
    if (v >= N) return;
    int rs = g_rs[v];
    int dg = g_degcnt[v];
    const float2* __restrict__ hp2 = (const float2*)g_hp;
    const bool act = (lane < W);
    const float2 zero2 = {0.f, 0.f};
    float a0 = 0.f, a1 = 0.f, b0 = 0.f, b1 = 0.f;

    for (int j0 = 0; j0 < dg; j0 += 32) {
        int jj = j0 + lane;
        int sv = (jj < dg) ? __ldg(&g_csrc[rs + jj]) : 0;
        int m = dg - j0; if (m > 32) m = 32;
        int k = 0;
        for (; k + 8 <= m; k += 8) {
            float2 t[8];
            // phase 1: issue all 8 loads (independent, batched)
            #pragma unroll
            for (int u = 0; u < 8; u++) {
                int s = __shfl_sync(0xffffffffu, sv, k + u);
                t[u] = act ? __ldg(&hp2[(size_t)s * W + lane]) : zero2;
            }
            // phase 2: accumulate (two chains)
            #pragma unroll
            for (int u = 0; u < 8; u += 2) {
                a0 += t[u].x;     a1 += t[u].y;
                b0 += t[u + 1].x; b1 += t[u + 1].y;
            }
        }
        for (; k < m; k++) {
            int s = __shfl_sync(0xffffffffu, sv, k);
            if (act) {
                float2 f = __ldg(&hp2[(size_t)s * W + lane]);
                a0 += f.x; a1 += f.y;
            }
        }
    }
    if (act) {
        float2 f = __ldg(&hp2[(size_t)v * W + lane]);   // self loop
        a0 += b0 + f.x; a1 += b1 + f.y;
        float ds = g_dis[v];
        float2 o;
        o.x = fmaxf(ds * a0 + __ldg(&bias[2 * lane]), 0.f);
        o.y = fmaxf(ds * a1 + __ldg(&bias[2 * lane + 1]), 0.f);
        *(float2*)(g_out + (size_t)v * D + 2 * lane) = o;
    }
}

// -------- mean pool --------
__global__ void pool_kernel(const int* __restrict__ batch, int N) {
    const int CH = 64;
    int n0 = blockIdx.x * CH;
    int c  = threadIdx.x;
    int nend = n0 + CH; if (nend > N) nend = N;
    float acc = 0.f, cacc = 0.f;
    int curg = -1;
    for (int n = n0; n < nend; n++) {
        int g = batch[n];
        if (g != curg) {
            if (curg >= 0) {
                atomicAdd(&g_pool[curg * DMAX + c], acc);
                if (c == 0) atomicAdd(&g_cnt[curg], cacc);
            }
            curg = g; acc = 0.f; cacc = 0.f;
        }
        acc  += g_out[(size_t)n * DMAX + c];
        cacc += 1.0f;
    }
    if (curg >= 0) {
        atomicAdd(&g_pool[curg * DMAX + c], acc);
        if (c == 0) atomicAdd(&g_cnt[curg], cacc);
    }
}

// -------- MLP + softmax --------
__global__ void mlp_kernel(const float* __restrict__ fc1w, const float* __restrict__ fc1b,
                           const float* __restrict__ fc2w, const float* __restrict__ fc2b,
                           float* __restrict__ out) {
    int g = blockIdx.x * blockDim.x + threadIdx.x;
    if (g >= NGRAPH) return;
    float invc = 1.0f / fmaxf(g_cnt[g], 1.0f);
    float p[64];
    #pragma unroll
    for (int i = 0; i < 64; i++) p[i] = g_pool[g * DMAX + i] * invc;
    float z[32];
    #pragma unroll 4
    for (int j = 0; j < 32; j++) {
        float a = fc1b[j];
        #pragma unroll
        for (int i = 0; i < 64; i++) a += p[i] * fc1w[i * 32 + j];
        z[j] = fmaxf(a, 0.f);
    }
    float l[16]; float mx = -1e30f;
    #pragma unroll
    for (int k = 0; k < 16; k++) {
        float a = fc2b[k];
        #pragma unroll
        for (int j = 0; j < 32; j++) a += z[j] * fc2w[j * 16 + k];
        l[k] = a; mx = fmaxf(mx, a);
    }
    float s = 0.f;
    #pragma unroll
    for (int k = 0; k < 16; k++) { l[k] = expf(l[k] - mx); s += l[k]; }
    float invs = 1.0f / s;
    #pragma unroll
    for (int k = 0; k < 16; k++) out[g * 16 + k] = l[k] * invs;
}

extern "C" void kernel_launch(void* const* d_in, const int* in_sizes, int n_in,
                              void* d_out, int out_size) {
    const float* x     = (const float*)d_in[0];
    const int*   eidx  = (const int*)d_in[1];
    const int*   batch = (const int*)d_in[2];
    const float* W1 = (const float*)d_in[3];
    const float* b1 = (const float*)d_in[4];
    const float* W2 = (const float*)d_in[5];
    const float* b2 = (const float*)d_in[6];
    const float* W3 = (const float*)d_in[7];
    const float* b3 = (const float*)d_in[8];
    const float* fc1w = (const float*)d_in[9];
    const float* fc1b = (const float*)d_in[10];
    const float* fc2w = (const float*)d_in[11];
    const float* fc2b = (const float*)d_in[12];
    float* out = (float*)d_out;

    int N = in_sizes[0] / 128;
    int E = in_sizes[1] / 2;
    const int* src = eidx;
    const int* dst = eidx + E;

    cudaStream_t s2;
    cudaStreamCreateWithFlags(&s2, cudaStreamNonBlocking);
    cudaEvent_t evDeg, evG1;
    cudaEventCreateWithFlags(&evDeg, cudaEventDisableTiming);
    cudaEventCreateWithFlags(&evG1, cudaEventDisableTiming);

    void *p_deg, *p_pool, *p_cnt;
    cudaGetSymbolAddress(&p_deg, g_degcnt);
    cudaGetSymbolAddress(&p_pool, g_pool);
    cudaGetSymbolAddress(&p_cnt, g_cnt);
    cudaMemsetAsync(p_deg, 0, (size_t)N * 4, 0);
    cudaMemsetAsync(p_pool, 0, (size_t)NGRAPH * DMAX * 4, 0);
    cudaMemsetAsync(p_cnt, 0, (size_t)NGRAPH * 4, 0);

    deg_kernel<<<(E + 255) / 256, 256>>>(dst, E);
    cudaEventRecord(evDeg, 0);

    // fork: dis -> gemm1 while CSR builds
    cudaStreamWaitEvent(s2, evDeg, 0);
    dis_kernel<<<(N + 255) / 256, 256, 0, s2>>>(N);
    gemm_kernel<128, 32, 16><<<(N + 15) / 16, 128, 0, s2>>>(x, 0, W1, N);
    cudaEventRecord(evG1, s2);

    int nb = (N + 511) / 512;
    scan1_kernel<<<nb, 512>>>(N);
    scan2_kernel<<<1, 512>>>(nb);
    scan3_kernel<<<(N + 255) / 256, 256>>>(N);
    fill_csr_kernel<<<(E + 255) / 256, 256>>>(src, dst, E);

    cudaStreamWaitEvent(0, evG1, 0);

    int gth_blocks = (N + 7) / 8;
    int gemm_blocks = (N + 15) / 16;

    gather_kernel<32><<<gth_blocks, 256>>>(b1, N);
    gemm_kernel<32, 48, 16><<<gemm_blocks, 192>>>(nullptr, 1, W2, N);
    gather_kernel<48><<<gth_blocks, 256>>>(b2, N);
    gemm_kernel<48, 64, 16><<<gemm_blocks, 256>>>(nullptr, 1, W3, N);
    gather_kernel<64><<<gth_blocks, 256>>>(b3, N);

    pool_kernel<<<(N + 63) / 64, 64>>>(batch, N);
    mlp_kernel<<<(NGRAPH + 255) / 256, 256>>>(fc1w, fc1b, fc2w, fc2b, out);
}

// round 10
// speedup vs baseline: 1.1260x; 1.1260x over previous
#include <cuda_runtime.h>
#include <cuda_bf16.h>

#define MAXN 100000
#define MAXE 3200000
#define NGRAPH 512
#define DMAX 64
#define SCANB 512
#define MAXSB 512

// -------- device scratch --------
__device__ int   g_degcnt[MAXN];
__device__ int   g_rs    [MAXN];
__device__ int   g_cursor[MAXN];
__device__ unsigned long long g_scanstate[MAXSB];  // (flag<<32)|value
__device__ int   g_csrc  [MAXE];
__device__ float g_hp    [MAXN * DMAX];
__device__ float g_out   [MAXN * DMAX];
__device__ float g_pool  [NGRAPH * DMAX];
__device__ float g_cnt   [NGRAPH];

// -------- degree --------
__global__ void deg_kernel(const int* __restrict__ dst, int E) {
    int i = blockIdx.x * blockDim.x + threadIdx.x;
    if (i < E) atomicAdd(&g_degcnt[__ldg(&dst[i])], 1);
}

// -------- single-pass exclusive scan (decoupled lookback) --------
// Lookback waits only on lower block ids (scheduled no later) -> deadlock-free.
__global__ void scan_kernel(int N) {
    __shared__ int s[SCANB];
    __shared__ int s_prev;
    int t = threadIdx.x, b = blockIdx.x;
    int i = b * SCANB + t;
    int v = (i < N) ? g_degcnt[i] : 0;
    s[t] = v; __syncthreads();
    for (int o = 1; o < SCANB; o <<= 1) {
        int u = (t >= o) ? s[t - o] : 0;
        __syncthreads(); s[t] += u; __syncthreads();
    }
    int total = s[SCANB - 1];

    if (t == 0) {
        unsigned long long pkt = (b == 0)
            ? (((unsigned long long)2 << 32) | (unsigned)total)
            : (((unsigned long long)1 << 32) | (unsigned)total);
        __threadfence();
        atomicExch(&g_scanstate[b], pkt);
    }

    if (b > 0) {
        if (t < 32) {
            int prev = 0;
            int look = b - 1;
            while (true) {
                int idx = look - t;
                unsigned long long pkt;
                unsigned flag; int val;
                do {
                    pkt = (idx >= 0) ? atomicAdd(&g_scanstate[idx], 0ULL)
                                     : ((unsigned long long)2 << 32);
                    flag = (unsigned)(pkt >> 32);
                } while (__any_sync(0xffffffffu, flag == 0));
                val = (idx >= 0) ? (int)(unsigned)pkt : 0;
                unsigned pmask = __ballot_sync(0xffffffffu, flag == 2);
                if (pmask) {
                    int t2 = __ffs(pmask) - 1;
                    int contrib = (t <= t2) ? val : 0;
                    #pragma unroll
                    for (int o = 16; o; o >>= 1) contrib += __shfl_down_sync(0xffffffffu, contrib, o);
                    contrib = __shfl_sync(0xffffffffu, contrib, 0);
                    prev += contrib;
                    break;
                } else {
                    int contrib = val;
                    #pragma unroll
                    for (int o = 16; o; o >>= 1) contrib += __shfl_down_sync(0xffffffffu, contrib, o);
                    contrib = __shfl_sync(0xffffffffu, contrib, 0);
                    prev += contrib;
                    look -= 32;
                }
            }
            if (t == 0) {
                unsigned long long pkt = ((unsigned long long)2 << 32) | (unsigned)(prev + total);
                __threadfence();
                atomicExch(&g_scanstate[b], pkt);
                s_prev = prev;
            }
        }
        __syncthreads();
    } else {
        if (t == 0) s_prev = 0;
        __syncthreads();
    }
    int prev = s_prev;
    if (i < N) {
        int r = prev + s[t] - v;
        g_rs[i] = r;
        g_cursor[i] = r;
    }
}

// -------- CSR fill --------
__global__ void fill_csr_kernel(const int* __restrict__ src,
                                const int* __restrict__ dst, int E) {
    int i = blockIdx.x * blockDim.x + threadIdx.x;
    if (i < E) {
        int d = __ldg(&dst[i]);
        int p = atomicAdd(&g_cursor[d], 1);
        g_csrc[p] = __ldg(&src[i]);
    }
}

// -------- GEMM + pre-scale: hp = (X@W) * rsqrt(deg+1) --------
template<int K, int M, int R>
__global__ void gemm_kernel(const float* __restrict__ Xext, int xsel,
                            const float* __restrict__ W, int N) {
    constexpr int G = M / 4;
    __shared__ float4 sw[K * G];
    __shared__ float  sx[R * (K + 1)];
    const float* __restrict__ X = xsel ? g_out : Xext;
    int tid = threadIdx.x;
    const float4* W4 = (const float4*)W;
    for (int i = tid; i < K * G; i += blockDim.x) sw[i] = W4[i];
    int row0 = blockIdx.x * R;
    int nrows = N - row0; if (nrows > R) nrows = R;
    if (nrows <= 0) return;
    for (int i = tid; i < nrows * K; i += blockDim.x) {
        int r = i / K, k = i - r * K;
        sx[r * (K + 1) + k] = X[(size_t)(row0 + r) * K + k];
    }
    __syncthreads();
    int r = tid / G, g = tid - r * G;
    if (r < nrows) {
        float4 acc = {0.f, 0.f, 0.f, 0.f};
        const float* xr = &sx[r * (K + 1)];
        #pragma unroll 8
        for (int k = 0; k < K; k++) {
            float xv = xr[k];
            float4 wv = sw[k * G + g];
            acc.x += xv * wv.x; acc.y += xv * wv.y;
            acc.z += xv * wv.z; acc.w += xv * wv.w;
        }
        float ds = rsqrtf((float)g_degcnt[row0 + r] + 1.0f);
        acc.x *= ds; acc.y *= ds; acc.z *= ds; acc.w *= ds;
        ((float4*)g_hp)[(size_t)(row0 + r) * G + g] = acc;
    }
}

// -------- gather + finalize (R6 form, proven fastest) --------
template<int D>
__global__ void __launch_bounds__(256)
gather_kernel(const float* __restrict__ bias, int N) {
    int v = (int)((blockIdx.x * blockDim.x + threadIdx.x) >> 5);
    int lane = threadIdx.x & 31;
    if (v >= N) return;
    int rs = g_rs[v];
    int dg = g_degcnt[v];
    float a0 = 0.f, a1 = 0.f;
    const float* __restrict__ hp = g_hp;

    for (int j0 = 0; j0 < dg; j0 += 32) {
        int jj = j0 + lane;
        int sv = (jj < dg) ? __ldg(&g_csrc[rs + jj]) : 0;
        int cnt = dg - j0; if (cnt > 32) cnt = 32;
        if (cnt == 32) {
            #pragma unroll 8
            for (int k = 0; k < 32; k++) {
                int s = __shfl_sync(0xffffffffu, sv, k);
                if (D == 64) {
                    float2 h = *(const float2*)(hp + (size_t)s * 64 + lane * 2);
                    a0 += h.x; a1 += h.y;
                } else if (D == 48) {
                    a0 += hp[(size_t)s * 48 + lane];
                    if (lane < 16) a1 += hp[(size_t)s * 48 + 32 + lane];
                } else {
                    a0 += hp[(size_t)s * 32 + lane];
                }
            }
        } else {
            for (int k = 0; k < cnt; k++) {
                int s = __shfl_sync(0xffffffffu, sv, k);
                if (D == 64) {
                    float2 h = *(const float2*)(hp + (size_t)s * 64 + lane * 2);
                    a0 += h.x; a1 += h.y;
                } else if (D == 48) {
                    a0 += hp[(size_t)s * 48 + lane];
                    if (lane < 16) a1 += hp[(size_t)s * 48 + 32 + lane];
                } else {
                    a0 += hp[(size_t)s * 32 + lane];
                }
            }
        }
    }
    // self loop
    if (D == 64) {
        float2 h = *(const float2*)(hp + (size_t)v * 64 + lane * 2);
        a0 += h.x; a1 += h.y;
    } else if (D == 48) {
        a0 += hp[(size_t)v * 48 + lane];
        if (lane < 16) a1 += hp[(size_t)v * 48 + 32 + lane];
    } else {
        a0 += hp[(size_t)v * 32 + lane];
    }
    float ds = rsqrtf((float)dg + 1.0f);
    if (D == 64) {
        float2 o;
        o.x = fmaxf(ds * a0 + __ldg(&bias[lane * 2]), 0.f);
        o.y = fmaxf(ds * a1 + __ldg(&bias[lane * 2 + 1]), 0.f);
        *(float2*)(g_out + (size_t)v * 64 + lane * 2) = o;
    } else if (D == 48) {
        g_out[(size_t)v * 48 + lane] = fmaxf(ds * a0 + __ldg(&bias[lane]), 0.f);
        if (lane < 16)
            g_out[(size_t)v * 48 + 32 + lane] = fmaxf(ds * a1 + __ldg(&bias[32 + lane]), 0.f);
    } else {
        g_out[(size_t)v * 32 + lane] = fmaxf(ds * a0 + __ldg(&bias[lane]), 0.f);
    }
}

// -------- mean pool --------
__global__ void pool_kernel(const int* __restrict__ batch, int N) {
    const int CH = 64;
    int n0 = blockIdx.x * CH;
    int c  = threadIdx.x;
    int nend = n0 + CH; if (nend > N) nend = N;
    float acc = 0.f, cacc = 0.f;
    int curg = -1;
    for (int n = n0; n < nend; n++) {
        int g = batch[n];
        if (g != curg) {
            if (curg >= 0) {
                atomicAdd(&g_pool[curg * DMAX + c], acc);
                if (c == 0) atomicAdd(&g_cnt[curg], cacc);
            }
            curg = g; acc = 0.f; cacc = 0.f;
        }
        acc  += g_out[(size_t)n * DMAX + c];
        cacc += 1.0f;
    }
    if (curg >= 0) {
        atomicAdd(&g_pool[curg * DMAX + c], acc);
        if (c == 0) atomicAdd(&g_cnt[curg], cacc);
    }
}

// -------- MLP + softmax --------
__global__ void mlp_kernel(const float* __restrict__ fc1w, const float* __restrict__ fc1b,
                           const float* __restrict__ fc2w, const float* __restrict__ fc2b,
                           float* __restrict__ out) {
    int g = blockIdx.x * blockDim.x + threadIdx.x;
    if (g >= NGRAPH) return;
    float invc = 1.0f / fmaxf(g_cnt[g], 1.0f);
    float p[64];
    #pragma unroll
    for (int i = 0; i < 64; i++) p[i] = g_pool[g * DMAX + i] * invc;
    float z[32];
    #pragma unroll 4
    for (int j = 0; j < 32; j++) {
        float a = fc1b[j];
        #pragma unroll
        for (int i = 0; i < 64; i++) a += p[i] * fc1w[i * 32 + j];
        z[j] = fmaxf(a, 0.f);
    }
    float l[16]; float mx = -1e30f;
    #pragma unroll
    for (int k = 0; k < 16; k++) {
        float a = fc2b[k];
        #pragma unroll
        for (int j = 0; j < 32; j++) a += z[j] * fc2w[j * 16 + k];
        l[k] = a; mx = fmaxf(mx, a);
    }
    float s = 0.f;
    #pragma unroll
    for (int k = 0; k < 16; k++) { l[k] = expf(l[k] - mx); s += l[k]; }
    float invs = 1.0f / s;
    #pragma unroll
    for (int k = 0; k < 16; k++) out[g * 16 + k] = l[k] * invs;
}

extern "C" void kernel_launch(void* const* d_in, const int* in_sizes, int n_in,
                              void* d_out, int out_size) {
    const float* x     = (const float*)d_in[0];
    const int*   eidx  = (const int*)d_in[1];
    const int*   batch = (const int*)d_in[2];
    const float* W1 = (const float*)d_in[3];
    const float* b1 = (const float*)d_in[4];
    const float* W2 = (const float*)d_in[5];
    const float* b2 = (const float*)d_in[6];
    const float* W3 = (const float*)d_in[7];
    const float* b3 = (const float*)d_in[8];
    const float* fc1w = (const float*)d_in[9];
    const float* fc1b = (const float*)d_in[10];
    const float* fc2w = (const float*)d_in[11];
    const float* fc2b = (const float*)d_in[12];
    float* out = (float*)d_out;

    int N = in_sizes[0] / 128;
    int E = in_sizes[1] / 2;
    const int* src = eidx;
    const int* dst = eidx + E;

    cudaStream_t s2;
    cudaStreamCreateWithFlags(&s2, cudaStreamNonBlocking);
    cudaEvent_t evDeg, evG1;
    cudaEventCreateWithFlags(&evDeg, cudaEventDisableTiming);
    cudaEventCreateWithFlags(&evG1, cudaEventDisableTiming);

    void *p_deg, *p_pool, *p_cnt, *p_scan;
    cudaGetSymbolAddress(&p_deg, g_degcnt);
    cudaGetSymbolAddress(&p_pool, g_pool);
    cudaGetSymbolAddress(&p_cnt, g_cnt);
    cudaGetSymbolAddress(&p_scan, g_scanstate);
    cudaMemsetAsync(p_deg, 0, (size_t)N * 4, 0);
    cudaMemsetAsync(p_pool, 0, (size_t)NGRAPH * DMAX * 4, 0);
    cudaMemsetAsync(p_cnt, 0, (size_t)NGRAPH * 4, 0);
    cudaMemsetAsync(p_scan, 0, (size_t)MAXSB * 8, 0);

    deg_kernel<<<(E + 255) / 256, 256>>>(dst, E);
    cudaEventRecord(evDeg, 0);

    // fork: gemm1 (computes dis inline) while CSR builds
    cudaStreamWaitEvent(s2, evDeg, 0);
    gemm_kernel<128, 32, 16><<<(N + 15) / 16, 128, 0, s2>>>(x, 0, W1, N);
    cudaEventRecord(evG1, s2);

    int nb = (N + SCANB - 1) / SCANB;
    scan_kernel<<<nb, SCANB>>>(N);
    fill_csr_kernel<<<(E + 255) / 256, 256>>>(src, dst, E);

    cudaStreamWaitEvent(0, evG1, 0);

    int gth_blocks = (N + 7) / 8;
    int gemm_blocks = (N + 15) / 16;

    gather_kernel<32><<<gth_blocks, 256>>>(b1, N);
    gemm_kernel<32, 48, 16><<<gemm_blocks, 192>>>(nullptr, 1, W2, N);
    gather_kernel<48><<<gth_blocks, 256>>>(b2, N);
    gemm_kernel<48, 64, 16><<<gemm_blocks, 256>>>(nullptr, 1, W3, N);
    gather_kernel<64><<<gth_blocks, 256>>>(b3, N);

    pool_kernel<<<(N + 63) / 64, 64>>>(batch, N);
    mlp_kernel<<<(NGRAPH + 255) / 256, 256>>>(fc1w, fc1b, fc2w, fc2b, out);
}

// round 11
// speedup vs baseline: 1.1321x; 1.0054x over previous
#include <cuda_runtime.h>
#include <cuda_bf16.h>

#define MAXN 100000
#define MAXE 3200000
#define NGRAPH 512
#define DMAX 64
#define SCANB 512
#define MAXSB 512

// -------- device scratch --------
__device__ int   g_degcnt[MAXN];
__device__ int   g_rs    [MAXN];
__device__ int   g_cursor[MAXN];
__device__ unsigned long long g_scanstate[MAXSB];
__device__ int   g_csrc  [MAXE];
__device__ float g_hp    [MAXN * DMAX];   // buffer A
__device__ float g_out   [MAXN * DMAX];   // buffer B
__device__ float g_pool  [NGRAPH * DMAX];
__device__ float g_cnt   [NGRAPH];

// -------- degree --------
__global__ void deg_kernel(const int* __restrict__ dst, int E) {
    int i = blockIdx.x * blockDim.x + threadIdx.x;
    if (i < E) atomicAdd(&g_degcnt[__ldg(&dst[i])], 1);
}

// -------- single-pass exclusive scan (decoupled lookback) --------
__global__ void scan_kernel(int N) {
    __shared__ int s[SCANB];
    __shared__ int s_prev;
    int t = threadIdx.x, b = blockIdx.x;
    int i = b * SCANB + t;
    int v = (i < N) ? g_degcnt[i] : 0;
    s[t] = v; __syncthreads();
    for (int o = 1; o < SCANB; o <<= 1) {
        int u = (t >= o) ? s[t - o] : 0;
        __syncthreads(); s[t] += u; __syncthreads();
    }
    int total = s[SCANB - 1];

    if (t == 0) {
        unsigned long long pkt = (b == 0)
            ? (((unsigned long long)2 << 32) | (unsigned)total)
            : (((unsigned long long)1 << 32) | (unsigned)total);
        __threadfence();
        atomicExch(&g_scanstate[b], pkt);
    }

    if (b > 0) {
        if (t < 32) {
            int prev = 0;
            int look = b - 1;
            while (true) {
                int idx = look - t;
                unsigned long long pkt;
                unsigned flag; int val;
                do {
                    pkt = (idx >= 0) ? atomicAdd(&g_scanstate[idx], 0ULL)
                                     : ((unsigned long long)2 << 32);
                    flag = (unsigned)(pkt >> 32);
                } while (__any_sync(0xffffffffu, flag == 0));
                val = (idx >= 0) ? (int)(unsigned)pkt : 0;
                unsigned pmask = __ballot_sync(0xffffffffu, flag == 2);
                if (pmask) {
                    int t2 = __ffs(pmask) - 1;
                    int contrib = (t <= t2) ? val : 0;
                    #pragma unroll
                    for (int o = 16; o; o >>= 1) contrib += __shfl_down_sync(0xffffffffu, contrib, o);
                    contrib = __shfl_sync(0xffffffffu, contrib, 0);
                    prev += contrib;
                    break;
                } else {
                    int contrib = val;
                    #pragma unroll
                    for (int o = 16; o; o >>= 1) contrib += __shfl_down_sync(0xffffffffu, contrib, o);
                    contrib = __shfl_sync(0xffffffffu, contrib, 0);
                    prev += contrib;
                    look -= 32;
                }
            }
            if (t == 0) {
                unsigned long long pkt = ((unsigned long long)2 << 32) | (unsigned)(prev + total);
                __threadfence();
                atomicExch(&g_scanstate[b], pkt);
                s_prev = prev;
            }
        }
        __syncthreads();
    } else {
        if (t == 0) s_prev = 0;
        __syncthreads();
    }
    int prev = s_prev;
    if (i < N) {
        int r = prev + s[t] - v;
        g_rs[i] = r;
        g_cursor[i] = r;
    }
}

// -------- CSR fill --------
__global__ void fill_csr_kernel(const int* __restrict__ src,
                                const int* __restrict__ dst, int E) {
    int i = blockIdx.x * blockDim.x + threadIdx.x;
    if (i < E) {
        int d = __ldg(&dst[i]);
        int p = atomicAdd(&g_cursor[d], 1);
        g_csrc[p] = __ldg(&src[i]);
    }
}

// -------- GEMM with fused epilogue --------
// EPI=0: src=Xext, dst=g_hp,  v = acc * dis                (layer-1 pre-gather)
// EPI=1: src=g_hp, dst=g_out, v = relu(acc + b) * dis      (layer-2 post-gather)
// EPI=2: src=g_hp, dst=g_out, v = relu(acc + b)            (layer-3 post-gather)
template<int K, int M, int R, int EPI>
__global__ void gemm_kernel(const float* __restrict__ Xext,
                            const float* __restrict__ W,
                            const float* __restrict__ bias, int N) {
    constexpr int G = M / 4;
    __shared__ float4 sw[K * G];
    __shared__ float  sx[R * (K + 1)];
    const float* __restrict__ X = (EPI == 0) ? Xext : g_hp;
    float* __restrict__ DST = (EPI == 0) ? g_hp : g_out;
    int tid = threadIdx.x;
    const float4* W4 = (const float4*)W;
    for (int i = tid; i < K * G; i += blockDim.x) sw[i] = W4[i];
    int row0 = blockIdx.x * R;
    int nrows = N - row0; if (nrows > R) nrows = R;
    if (nrows <= 0) return;
    for (int i = tid; i < nrows * K; i += blockDim.x) {
        int r = i / K, k = i - r * K;
        sx[r * (K + 1) + k] = X[(size_t)(row0 + r) * K + k];
    }
    __syncthreads();
    int r = tid / G, g = tid - r * G;
    if (r < nrows) {
        float4 acc = {0.f, 0.f, 0.f, 0.f};
        const float* xr = &sx[r * (K + 1)];
        #pragma unroll 8
        for (int k = 0; k < K; k++) {
            float xv = xr[k];
            float4 wv = sw[k * G + g];
            acc.x += xv * wv.x; acc.y += xv * wv.y;
            acc.z += xv * wv.z; acc.w += xv * wv.w;
        }
        if (EPI == 0) {
            float ds = rsqrtf((float)g_degcnt[row0 + r] + 1.0f);
            acc.x *= ds; acc.y *= ds; acc.z *= ds; acc.w *= ds;
        } else {
            acc.x = fmaxf(acc.x + __ldg(&bias[4 * g]), 0.f);
            acc.y = fmaxf(acc.y + __ldg(&bias[4 * g + 1]), 0.f);
            acc.z = fmaxf(acc.z + __ldg(&bias[4 * g + 2]), 0.f);
            acc.w = fmaxf(acc.w + __ldg(&bias[4 * g + 3]), 0.f);
            if (EPI == 1) {
                float ds = rsqrtf((float)g_degcnt[row0 + r] + 1.0f);
                acc.x *= ds; acc.y *= ds; acc.z *= ds; acc.w *= ds;
            }
        }
        ((float4*)DST)[(size_t)(row0 + r) * G + g] = acc;
    }
}

// -------- gather (R6 memory pattern) with fused epilogue --------
// EPI=1: src=g_hp,  dst=g_out, o = dis * relu(dis * a + bias)   (layer 1)
// EPI=2: src=g_out, dst=g_hp,  o = dis * a                      (layers 2,3 pre-GEMM)
template<int D, int EPI>
__global__ void __launch_bounds__(256)
gather_kernel(const float* __restrict__ bias, int N) {
    int v = (int)((blockIdx.x * blockDim.x + threadIdx.x) >> 5);
    int lane = threadIdx.x & 31;
    if (v >= N) return;
    int rs = g_rs[v];
    int dg = g_degcnt[v];
    float a0 = 0.f, a1 = 0.f;
    const float* __restrict__ hp = (EPI == 1) ? g_hp : g_out;
    float* __restrict__ dstbuf = (EPI == 1) ? g_out : g_hp;

    for (int j0 = 0; j0 < dg; j0 += 32) {
        int jj = j0 + lane;
        int sv = (jj < dg) ? __ldg(&g_csrc[rs + jj]) : 0;
        int cnt = dg - j0; if (cnt > 32) cnt = 32;
        if (cnt == 32) {
            #pragma unroll 8
            for (int k = 0; k < 32; k++) {
                int s = __shfl_sync(0xffffffffu, sv, k);
                if (D == 48) {
                    a0 += hp[(size_t)s * 48 + lane];
                    if (lane < 16) a1 += hp[(size_t)s * 48 + 32 + lane];
                } else {
                    a0 += hp[(size_t)s * 32 + lane];
                }
            }
        } else {
            for (int k = 0; k < cnt; k++) {
                int s = __shfl_sync(0xffffffffu, sv, k);
                if (D == 48) {
                    a0 += hp[(size_t)s * 48 + lane];
                    if (lane < 16) a1 += hp[(size_t)s * 48 + 32 + lane];
                } else {
                    a0 += hp[(size_t)s * 32 + lane];
                }
            }
        }
    }
    // self loop
    if (D == 48) {
        a0 += hp[(size_t)v * 48 + lane];
        if (lane < 16) a1 += hp[(size_t)v * 48 + 32 + lane];
    } else {
        a0 += hp[(size_t)v * 32 + lane];
    }
    float ds = rsqrtf((float)dg + 1.0f);
    if (EPI == 1) {
        float o = ds * fmaxf(ds * a0 + __ldg(&bias[lane]), 0.f);
        dstbuf[(size_t)v * D + lane] = o;
        if (D == 48 && lane < 16)
            dstbuf[(size_t)v * D + 32 + lane] =
                ds * fmaxf(ds * a1 + __ldg(&bias[32 + lane]), 0.f);
    } else {
        dstbuf[(size_t)v * D + lane] = ds * a0;
        if (D == 48 && lane < 16)
            dstbuf[(size_t)v * D + 32 + lane] = ds * a1;
    }
}

// -------- mean pool (reads h3 in g_out) --------
__global__ void pool_kernel(const int* __restrict__ batch, int N) {
    const int CH = 64;
    int n0 = blockIdx.x * CH;
    int c  = threadIdx.x;
    int nend = n0 + CH; if (nend > N) nend = N;
    float acc = 0.f, cacc = 0.f;
    int curg = -1;
    for (int n = n0; n < nend; n++) {
        int g = batch[n];
        if (g != curg) {
            if (curg >= 0) {
                atomicAdd(&g_pool[curg * DMAX + c], acc);
                if (c == 0) atomicAdd(&g_cnt[curg], cacc);
            }
            curg = g; acc = 0.f; cacc = 0.f;
        }
        acc  += g_out[(size_t)n * DMAX + c];
        cacc += 1.0f;
    }
    if (curg >= 0) {
        atomicAdd(&g_pool[curg * DMAX + c], acc);
        if (c == 0) atomicAdd(&g_cnt[curg], cacc);
    }
}

// -------- MLP + softmax --------
__global__ void mlp_kernel(const float* __restrict__ fc1w, const float* __restrict__ fc1b,
                           const float* __restrict__ fc2w, const float* __restrict__ fc2b,
                           float* __restrict__ out) {
    int g = blockIdx.x * blockDim.x + threadIdx.x;
    if (g >= NGRAPH) return;
    float invc = 1.0f / fmaxf(g_cnt[g], 1.0f);
    float p[64];
    #pragma unroll
    for (int i = 0; i < 64; i++) p[i] = g_pool[g * DMAX + i] * invc;
    float z[32];
    #pragma unroll 4
    for (int j = 0; j < 32; j++) {
        float a = fc1b[j];
        #pragma unroll
        for (int i = 0; i < 64; i++) a += p[i] * fc1w[i * 32 + j];
        z[j] = fmaxf(a, 0.f);
    }
    float l[16]; float mx = -1e30f;
    #pragma unroll
    for (int k = 0; k < 16; k++) {
        float a = fc2b[k];
        #pragma unroll
        for (int j = 0; j < 32; j++) a += z[j] * fc2w[j * 16 + k];
        l[k] = a; mx = fmaxf(mx, a);
    }
    float s = 0.f;
    #pragma unroll
    for (int k = 0; k < 16; k++) { l[k] = expf(l[k] - mx); s += l[k]; }
    float invs = 1.0f / s;
    #pragma unroll
    for (int k = 0; k < 16; k++) out[g * 16 + k] = l[k] * invs;
}

extern "C" void kernel_launch(void* const* d_in, const int* in_sizes, int n_in,
                              void* d_out, int out_size) {
    const float* x     = (const float*)d_in[0];
    const int*   eidx  = (const int*)d_in[1];
    const int*   batch = (const int*)d_in[2];
    const float* W1 = (const float*)d_in[3];
    const float* b1 = (const float*)d_in[4];
    const float* W2 = (const float*)d_in[5];
    const float* b2 = (const float*)d_in[6];
    const float* W3 = (const float*)d_in[7];
    const float* b3 = (const float*)d_in[8];
    const float* fc1w = (const float*)d_in[9];
    const float* fc1b = (const float*)d_in[10];
    const float* fc2w = (const float*)d_in[11];
    const float* fc2b = (const float*)d_in[12];
    float* out = (float*)d_out;

    int N = in_sizes[0] / 128;
    int E = in_sizes[1] / 2;
    const int* src = eidx;
    const int* dst = eidx + E;

    cudaStream_t s2;
    cudaStreamCreateWithFlags(&s2, cudaStreamNonBlocking);
    cudaEvent_t evDeg, evG1;
    cudaEventCreateWithFlags(&evDeg, cudaEventDisableTiming);
    cudaEventCreateWithFlags(&evG1, cudaEventDisableTiming);

    void *p_deg, *p_pool, *p_cnt, *p_scan;
    cudaGetSymbolAddress(&p_deg, g_degcnt);
    cudaGetSymbolAddress(&p_pool, g_pool);
    cudaGetSymbolAddress(&p_cnt, g_cnt);
    cudaGetSymbolAddress(&p_scan, g_scanstate);
    cudaMemsetAsync(p_deg, 0, (size_t)N * 4, 0);
    cudaMemsetAsync(p_pool, 0, (size_t)NGRAPH * DMAX * 4, 0);
    cudaMemsetAsync(p_cnt, 0, (size_t)NGRAPH * 4, 0);
    cudaMemsetAsync(p_scan, 0, (size_t)MAXSB * 8, 0);

    deg_kernel<<<(E + 255) / 256, 256>>>(dst, E);
    cudaEventRecord(evDeg, 0);

    // fork: gemm1 while CSR builds
    cudaStreamWaitEvent(s2, evDeg, 0);
    gemm_kernel<128, 32, 16, 0><<<(N + 15) / 16, 128, 0, s2>>>(x, W1, nullptr, N);
    cudaEventRecord(evG1, s2);

    int nb = (N + SCANB - 1) / SCANB;
    scan_kernel<<<nb, SCANB>>>(N);
    fill_csr_kernel<<<(E + 255) / 256, 256>>>(src, dst, E);

    cudaStreamWaitEvent(0, evG1, 0);

    int gth_blocks = (N + 7) / 8;
    int gemm_blocks = (N + 15) / 16;

    // L1: gather hp1(32) -> p1 in g_out
    gather_kernel<32, 1><<<gth_blocks, 256>>>(b1, N);
    // L2: gather p1(32) -> q2 in g_hp; gemm q2@W2 -> p2(48) in g_out
    gather_kernel<32, 2><<<gth_blocks, 256>>>(nullptr, N);
    gemm_kernel<32, 48, 16, 1><<<gemm_blocks, 192>>>(nullptr, W2, b2, N);
    // L3: gather p2(48) -> q3 in g_hp; gemm q3@W3 -> h3(64) in g_out
    gather_kernel<48, 2><<<gth_blocks, 256>>>(nullptr, N);
    gemm_kernel<48, 64, 16, 2><<<gemm_blocks, 256>>>(nullptr, W3, b3, N);

    pool_kernel<<<(N + 63) / 64, 64>>>(batch, N);
    mlp_kernel<<<(NGRAPH + 255) / 256, 256>>>(fc1w, fc1b, fc2w, fc2b, out);
}

// round 12
// speedup vs baseline: 1.2774x; 1.1284x over previous
#include <cuda_runtime.h>
#include <cuda_bf16.h>

#define MAXN 100000
#define MAXE 3200000
#define NGRAPH 512
#define DMAX 64
#define SCANB 512
#define MAXSB 512

// -------- device scratch --------
__device__ int   g_degcnt[MAXN];
__device__ int   g_rs    [MAXN];
__device__ int   g_cursor[MAXN];
__device__ unsigned long long g_scanstate[MAXSB];
__device__ int   g_csrc  [MAXE];
__device__ float g_hp    [MAXN * DMAX];   // buffer A
__device__ float g_out   [MAXN * DMAX];   // buffer B

// -------- degree --------
__global__ void deg_kernel(const int* __restrict__ dst, int E) {
    int i = blockIdx.x * blockDim.x + threadIdx.x;
    if (i < E) atomicAdd(&g_degcnt[__ldg(&dst[i])], 1);
}

// -------- single-pass exclusive scan (decoupled lookback) --------
__global__ void scan_kernel(int N) {
    __shared__ int s[SCANB];
    __shared__ int s_prev;
    int t = threadIdx.x, b = blockIdx.x;
    int i = b * SCANB + t;
    int v = (i < N) ? g_degcnt[i] : 0;
    s[t] = v; __syncthreads();
    for (int o = 1; o < SCANB; o <<= 1) {
        int u = (t >= o) ? s[t - o] : 0;
        __syncthreads(); s[t] += u; __syncthreads();
    }
    int total = s[SCANB - 1];

    if (t == 0) {
        unsigned long long pkt = (b == 0)
            ? (((unsigned long long)2 << 32) | (unsigned)total)
            : (((unsigned long long)1 << 32) | (unsigned)total);
        __threadfence();
        atomicExch(&g_scanstate[b], pkt);
    }

    if (b > 0) {
        if (t < 32) {
            int prev = 0;
            int look = b - 1;
            while (true) {
                int idx = look - t;
                unsigned long long pkt;
                unsigned flag; int val;
                do {
                    pkt = (idx >= 0) ? atomicAdd(&g_scanstate[idx], 0ULL)
                                     : ((unsigned long long)2 << 32);
                    flag = (unsigned)(pkt >> 32);
                } while (__any_sync(0xffffffffu, flag == 0));
                val = (idx >= 0) ? (int)(unsigned)pkt : 0;
                unsigned pmask = __ballot_sync(0xffffffffu, flag == 2);
                if (pmask) {
                    int t2 = __ffs(pmask) - 1;
                    int contrib = (t <= t2) ? val : 0;
                    #pragma unroll
                    for (int o = 16; o; o >>= 1) contrib += __shfl_down_sync(0xffffffffu, contrib, o);
                    contrib = __shfl_sync(0xffffffffu, contrib, 0);
                    prev += contrib;
                    break;
                } else {
                    int contrib = val;
                    #pragma unroll
                    for (int o = 16; o; o >>= 1) contrib += __shfl_down_sync(0xffffffffu, contrib, o);
                    contrib = __shfl_sync(0xffffffffu, contrib, 0);
                    prev += contrib;
                    look -= 32;
                }
            }
            if (t == 0) {
                unsigned long long pkt = ((unsigned long long)2 << 32) | (unsigned)(prev + total);
                __threadfence();
                atomicExch(&g_scanstate[b], pkt);
                s_prev = prev;
            }
        }
        __syncthreads();
    } else {
        if (t == 0) s_prev = 0;
        __syncthreads();
    }
    int prev = s_prev;
    if (i < N) {
        int r = prev + s[t] - v;
        g_rs[i] = r;
        g_cursor[i] = r;
    }
}

// -------- CSR fill --------
__global__ void fill_csr_kernel(const int* __restrict__ src,
                                const int* __restrict__ dst, int E) {
    int i = blockIdx.x * blockDim.x + threadIdx.x;
    if (i < E) {
        int d = __ldg(&dst[i]);
        int p = atomicAdd(&g_cursor[d], 1);
        g_csrc[p] = __ldg(&src[i]);
    }
}

// -------- GEMM with fused epilogue --------
// EPI=0: src=Xext, dst=g_hp,  v = acc * dis
// EPI=1: src=g_hp, dst=g_out, v = relu(acc + b) * dis
// EPI=2: src=g_hp, dst=g_out, v = relu(acc + b)
template<int K, int M, int R, int EPI>
__global__ void gemm_kernel(const float* __restrict__ Xext,
                            const float* __restrict__ W,
                            const float* __restrict__ bias, int N) {
    constexpr int G = M / 4;
    __shared__ float4 sw[K * G];
    __shared__ float  sx[R * (K + 1)];
    const float* __restrict__ X = (EPI == 0) ? Xext : g_hp;
    float* __restrict__ DST = (EPI == 0) ? g_hp : g_out;
    int tid = threadIdx.x;
    const float4* W4 = (const float4*)W;
    for (int i = tid; i < K * G; i += blockDim.x) sw[i] = W4[i];
    int row0 = blockIdx.x * R;
    int nrows = N - row0; if (nrows > R) nrows = R;
    if (nrows <= 0) return;
    for (int i = tid; i < nrows * K; i += blockDim.x) {
        int r = i / K, k = i - r * K;
        sx[r * (K + 1) + k] = X[(size_t)(row0 + r) * K + k];
    }
    __syncthreads();
    int r = tid / G, g = tid - r * G;
    if (r < nrows) {
        float4 acc = {0.f, 0.f, 0.f, 0.f};
        const float* xr = &sx[r * (K + 1)];
        #pragma unroll 8
        for (int k = 0; k < K; k++) {
            float xv = xr[k];
            float4 wv = sw[k * G + g];
            acc.x += xv * wv.x; acc.y += xv * wv.y;
            acc.z += xv * wv.z; acc.w += xv * wv.w;
        }
        if (EPI == 0) {
            float ds = rsqrtf((float)g_degcnt[row0 + r] + 1.0f);
            acc.x *= ds; acc.y *= ds; acc.z *= ds; acc.w *= ds;
        } else {
            acc.x = fmaxf(acc.x + __ldg(&bias[4 * g]), 0.f);
            acc.y = fmaxf(acc.y + __ldg(&bias[4 * g + 1]), 0.f);
            acc.z = fmaxf(acc.z + __ldg(&bias[4 * g + 2]), 0.f);
            acc.w = fmaxf(acc.w + __ldg(&bias[4 * g + 3]), 0.f);
            if (EPI == 1) {
                float ds = rsqrtf((float)g_degcnt[row0 + r] + 1.0f);
                acc.x *= ds; acc.y *= ds; acc.z *= ds; acc.w *= ds;
            }
        }
        ((float4*)DST)[(size_t)(row0 + r) * G + g] = acc;
    }
}

// -------- gather with fused epilogue --------
// EPI=1: src=g_hp,  dst=g_out, o = dis * relu(dis * a + bias)
// EPI=2: src=g_out, dst=g_hp,  o = dis * a
template<int D, int EPI>
__global__ void __launch_bounds__(256)
gather_kernel(const float* __restrict__ bias, int N) {
    int v = (int)((blockIdx.x * blockDim.x + threadIdx.x) >> 5);
    int lane = threadIdx.x & 31;
    if (v >= N) return;
    int rs = g_rs[v];
    int dg = g_degcnt[v];
    float a0 = 0.f, a1 = 0.f;
    const float* __restrict__ hp = (EPI == 1) ? g_hp : g_out;
    float* __restrict__ dstbuf = (EPI == 1) ? g_out : g_hp;

    for (int j0 = 0; j0 < dg; j0 += 32) {
        int jj = j0 + lane;
        int sv = (jj < dg) ? __ldg(&g_csrc[rs + jj]) : 0;
        int cnt = dg - j0; if (cnt > 32) cnt = 32;
        if (cnt == 32) {
            #pragma unroll 8
            for (int k = 0; k < 32; k++) {
                int s = __shfl_sync(0xffffffffu, sv, k);
                if (D == 48) {
                    a0 += hp[(size_t)s * 48 + lane];
                    if (lane < 16) a1 += hp[(size_t)s * 48 + 32 + lane];
                } else {
                    a0 += hp[(size_t)s * 32 + lane];
                }
            }
        } else {
            for (int k = 0; k < cnt; k++) {
                int s = __shfl_sync(0xffffffffu, sv, k);
                if (D == 48) {
                    a0 += hp[(size_t)s * 48 + lane];
                    if (lane < 16) a1 += hp[(size_t)s * 48 + 32 + lane];
                } else {
                    a0 += hp[(size_t)s * 32 + lane];
                }
            }
        }
    }
    // self loop
    if (D == 48) {
        a0 += hp[(size_t)v * 48 + lane];
        if (lane < 16) a1 += hp[(size_t)v * 48 + 32 + lane];
    } else {
        a0 += hp[(size_t)v * 32 + lane];
    }
    float ds = rsqrtf((float)dg + 1.0f);
    if (EPI == 1) {
        float o = ds * fmaxf(ds * a0 + __ldg(&bias[lane]), 0.f);
        dstbuf[(size_t)v * D + lane] = o;
        if (D == 48 && lane < 16)
            dstbuf[(size_t)v * D + 32 + lane] =
                ds * fmaxf(ds * a1 + __ldg(&bias[32 + lane]), 0.f);
    } else {
        dstbuf[(size_t)v * D + lane] = ds * a0;
        if (D == 48 && lane < 16)
            dstbuf[(size_t)v * D + 32 + lane] = ds * a1;
    }
}

// -------- fused pool + MLP + softmax: one block per graph --------
__global__ void pool_mlp_kernel(const int* __restrict__ batch, int N,
                                const float* __restrict__ fc1w, const float* __restrict__ fc1b,
                                const float* __restrict__ fc2w, const float* __restrict__ fc2b,
                                float* __restrict__ out) {
    int g = blockIdx.x;
    int tid = threadIdx.x;
    __shared__ float sp[256];
    __shared__ float p[64];
    __shared__ float z[32];

    // binary search graph bounds in sorted batch
    int lo = 0, hi = N;
    while (lo < hi) { int m = (lo + hi) >> 1; if (__ldg(&batch[m]) < g) lo = m + 1; else hi = m; }
    int start = lo;
    hi = N;
    while (lo < hi) { int m = (lo + hi) >> 1; if (__ldg(&batch[m]) < g + 1) lo = m + 1; else hi = m; }
    int end = lo;

    int c = tid & 63, part = tid >> 6;   // 4-way row split x 64 features
    float acc = 0.f;
    for (int n = start + part; n < end; n += 4)
        acc += g_out[(size_t)n * 64 + c];
    sp[part * 64 + c] = acc;
    __syncthreads();
    if (tid < 64) {
        float invc = 1.0f / fmaxf((float)(end - start), 1.0f);
        p[tid] = (sp[tid] + sp[64 + tid] + sp[128 + tid] + sp[192 + tid]) * invc;
    }
    __syncthreads();
    if (tid < 32) {
        float a = fc1b[tid];
        #pragma unroll
        for (int i = 0; i < 64; i++) a += p[i] * fc1w[i * 32 + tid];
        z[tid] = fmaxf(a, 0.f);
        __syncwarp();
        if (tid < 16) {
            float l = fc2b[tid];
            #pragma unroll
            for (int j = 0; j < 32; j++) l += z[j] * fc2w[j * 16 + tid];
            float mx = l;
            #pragma unroll
            for (int o = 8; o; o >>= 1) mx = fmaxf(mx, __shfl_xor_sync(0xffffu, mx, o));
            float e = expf(l - mx);
            float s = e;
            #pragma unroll
            for (int o = 8; o; o >>= 1) s += __shfl_xor_sync(0xffffu, s, o);
            out[g * 16 + tid] = e / s;
        }
    }
}

extern "C" void kernel_launch(void* const* d_in, const int* in_sizes, int n_in,
                              void* d_out, int out_size) {
    const float* x     = (const float*)d_in[0];
    const int*   eidx  = (const int*)d_in[1];
    const int*   batch = (const int*)d_in[2];
    const float* W1 = (const float*)d_in[3];
    const float* b1 = (const float*)d_in[4];
    const float* W2 = (const float*)d_in[5];
    const float* b2 = (const float*)d_in[6];
    const float* W3 = (const float*)d_in[7];
    const float* b3 = (const float*)d_in[8];
    const float* fc1w = (const float*)d_in[9];
    const float* fc1b = (const float*)d_in[10];
    const float* fc2w = (const float*)d_in[11];
    const float* fc2b = (const float*)d_in[12];
    float* out = (float*)d_out;

    int N = in_sizes[0] / 128;
    int E = in_sizes[1] / 2;
    const int* src = eidx;
    const int* dst = eidx + E;

    cudaStream_t s2;
    cudaStreamCreateWithFlags(&s2, cudaStreamNonBlocking);
    cudaEvent_t evDeg, evG1;
    cudaEventCreateWithFlags(&evDeg, cudaEventDisableTiming);
    cudaEventCreateWithFlags(&evG1, cudaEventDisableTiming);

    void *p_deg, *p_scan;
    cudaGetSymbolAddress(&p_deg, g_degcnt);
    cudaGetSymbolAddress(&p_scan, g_scanstate);
    cudaMemsetAsync(p_deg, 0, (size_t)N * 4, 0);
    cudaMemsetAsync(p_scan, 0, (size_t)MAXSB * 8, 0);

    deg_kernel<<<(E + 255) / 256, 256>>>(dst, E);
    cudaEventRecord(evDeg, 0);

    // fork: gemm1 while CSR builds
    cudaStreamWaitEvent(s2, evDeg, 0);
    gemm_kernel<128, 32, 16, 0><<<(N + 15) / 16, 128, 0, s2>>>(x, W1, nullptr, N);
    cudaEventRecord(evG1, s2);

    int nb = (N + SCANB - 1) / SCANB;
    scan_kernel<<<nb, SCANB>>>(N);
    fill_csr_kernel<<<(E + 255) / 256, 256>>>(src, dst, E);

    cudaStreamWaitEvent(0, evG1, 0);

    int gth_blocks = (N + 7) / 8;
    int gemm_blocks = (N + 15) / 16;

    // L1: gather hp1(32) -> p1 in g_out
    gather_kernel<32, 1><<<gth_blocks, 256>>>(b1, N);
    // L2: gather p1(32) -> q2 in g_hp; gemm q2@W2 -> p2(48) in g_out
    gather_kernel<32, 2><<<gth_blocks, 256>>>(nullptr, N);
    gemm_kernel<32, 48, 16, 1><<<gemm_blocks, 192>>>(nullptr, W2, b2, N);
    // L3: gather p2(48) -> q3 in g_hp; gemm q3@W3 -> h3(64) in g_out
    gather_kernel<48, 2><<<gth_blocks, 256>>>(nullptr, N);
    gemm_kernel<48, 64, 16, 2><<<gemm_blocks, 256>>>(nullptr, W3, b3, N);

    // fused pool + MLP + softmax
    pool_mlp_kernel<<<NGRAPH, 256>>>(batch, N, fc1w, fc1b, fc2w, fc2b, out);
}

// round 13
// speedup vs baseline: 1.2980x; 1.0161x over previous
#include <cuda_runtime.h>
#include <cuda_bf16.h>

#define MAXN 100000
#define MAXE 3200000
#define NGRAPH 512
#define DMAX 64
#define SCANB 512
#define MAXSB 512

// -------- device scratch --------
__device__ int   g_degcnt[MAXN];
__device__ int   g_rs    [MAXN];
__device__ int   g_cursor[MAXN];
__device__ unsigned long long g_scanstate[MAXSB];
__device__ int   g_csrc  [MAXE];
__device__ float g_hp    [MAXN * DMAX];   // buffer A
__device__ float g_out   [MAXN * DMAX];   // buffer B

// -------- degree --------
__global__ void deg_kernel(const int* __restrict__ dst, int E) {
    int i = blockIdx.x * blockDim.x + threadIdx.x;
    if (i < E) atomicAdd(&g_degcnt[__ldg(&dst[i])], 1);
}

// -------- single-pass exclusive scan (decoupled lookback) --------
__global__ void scan_kernel(int N) {
    __shared__ int s[SCANB];
    __shared__ int s_prev;
    int t = threadIdx.x, b = blockIdx.x;
    int i = b * SCANB + t;
    int v = (i < N) ? g_degcnt[i] : 0;
    s[t] = v; __syncthreads();
    for (int o = 1; o < SCANB; o <<= 1) {
        int u = (t >= o) ? s[t - o] : 0;
        __syncthreads(); s[t] += u; __syncthreads();
    }
    int total = s[SCANB - 1];

    if (t == 0) {
        unsigned long long pkt = (b == 0)
            ? (((unsigned long long)2 << 32) | (unsigned)total)
            : (((unsigned long long)1 << 32) | (unsigned)total);
        __threadfence();
        atomicExch(&g_scanstate[b], pkt);
    }

    if (b > 0) {
        if (t < 32) {
            int prev = 0;
            int look = b - 1;
            while (true) {
                int idx = look - t;
                unsigned long long pkt;
                unsigned flag; int val;
                do {
                    pkt = (idx >= 0) ? atomicAdd(&g_scanstate[idx], 0ULL)
                                     : ((unsigned long long)2 << 32);
                    flag = (unsigned)(pkt >> 32);
                } while (__any_sync(0xffffffffu, flag == 0));
                val = (idx >= 0) ? (int)(unsigned)pkt : 0;
                unsigned pmask = __ballot_sync(0xffffffffu, flag == 2);
                if (pmask) {
                    int t2 = __ffs(pmask) - 1;
                    int contrib = (t <= t2) ? val : 0;
                    #pragma unroll
                    for (int o = 16; o; o >>= 1) contrib += __shfl_down_sync(0xffffffffu, contrib, o);
                    contrib = __shfl_sync(0xffffffffu, contrib, 0);
                    prev += contrib;
                    break;
                } else {
                    int contrib = val;
                    #pragma unroll
                    for (int o = 16; o; o >>= 1) contrib += __shfl_down_sync(0xffffffffu, contrib, o);
                    contrib = __shfl_sync(0xffffffffu, contrib, 0);
                    prev += contrib;
                    look -= 32;
                }
            }
            if (t == 0) {
                unsigned long long pkt = ((unsigned long long)2 << 32) | (unsigned)(prev + total);
                __threadfence();
                atomicExch(&g_scanstate[b], pkt);
                s_prev = prev;
            }
        }
        __syncthreads();
    } else {
        if (t == 0) s_prev = 0;
        __syncthreads();
    }
    int prev = s_prev;
    if (i < N) {
        int r = prev + s[t] - v;
        g_rs[i] = r;
        g_cursor[i] = r;
    }
}

// -------- CSR fill --------
__global__ void fill_csr_kernel(const int* __restrict__ src,
                                const int* __restrict__ dst, int E) {
    int i = blockIdx.x * blockDim.x + threadIdx.x;
    if (i < E) {
        int d = __ldg(&dst[i]);
        int p = atomicAdd(&g_cursor[d], 1);
        g_csrc[p] = __ldg(&src[i]);
    }
}

// -------- GEMM with fused epilogue --------
// EPI=0: src=Xext, dst=g_hp,  v = acc * dis
// EPI=1: src=g_hp, dst=g_out, v = relu(acc + b) * dis
// EPI=2: src=g_hp, dst=g_out, v = relu(acc + b)
template<int K, int M, int R, int EPI>
__global__ void gemm_kernel(const float* __restrict__ Xext,
                            const float* __restrict__ W,
                            const float* __restrict__ bias, int N) {
    constexpr int G = M / 4;
    __shared__ float4 sw[K * G];
    __shared__ float  sx[R * (K + 1)];
    const float* __restrict__ X = (EPI == 0) ? Xext : g_hp;
    float* __restrict__ DST = (EPI == 0) ? g_hp : g_out;
    int tid = threadIdx.x;
    const float4* W4 = (const float4*)W;
    for (int i = tid; i < K * G; i += blockDim.x) sw[i] = W4[i];
    int row0 = blockIdx.x * R;
    int nrows = N - row0; if (nrows > R) nrows = R;
    if (nrows <= 0) return;
    for (int i = tid; i < nrows * K; i += blockDim.x) {
        int r = i / K, k = i - r * K;
        sx[r * (K + 1) + k] = X[(size_t)(row0 + r) * K + k];
    }
    __syncthreads();
    int r = tid / G, g = tid - r * G;
    if (r < nrows) {
        float4 acc = {0.f, 0.f, 0.f, 0.f};
        const float* xr = &sx[r * (K + 1)];
        #pragma unroll 8
        for (int k = 0; k < K; k++) {
            float xv = xr[k];
            float4 wv = sw[k * G + g];
            acc.x += xv * wv.x; acc.y += xv * wv.y;
            acc.z += xv * wv.z; acc.w += xv * wv.w;
        }
        if (EPI == 0) {
            float ds = rsqrtf((float)g_degcnt[row0 + r] + 1.0f);
            acc.x *= ds; acc.y *= ds; acc.z *= ds; acc.w *= ds;
        } else {
            acc.x = fmaxf(acc.x + __ldg(&bias[4 * g]), 0.f);
            acc.y = fmaxf(acc.y + __ldg(&bias[4 * g + 1]), 0.f);
            acc.z = fmaxf(acc.z + __ldg(&bias[4 * g + 2]), 0.f);
            acc.w = fmaxf(acc.w + __ldg(&bias[4 * g + 3]), 0.f);
            if (EPI == 1) {
                float ds = rsqrtf((float)g_degcnt[row0 + r] + 1.0f);
                acc.x *= ds; acc.y *= ds; acc.z *= ds; acc.w *= ds;
            }
        }
        ((float4*)DST)[(size_t)(row0 + r) * G + g] = acc;
    }
}

// -------- D=32 paired-edge gather: two 16-lane halves, one edge each --------
// Per 2 edges: 1 shfl + 1 LDG.64 + 2 FADD (vs 2 shfl + 2 LDG + 2 FADD).
// EPI=1: src=g_hp,  dst=g_out, o = dis * relu(dis * a + bias)
// EPI=2: src=g_out, dst=g_hp,  o = dis * a
template<int EPI>
__global__ void __launch_bounds__(256)
gather32_kernel(const float* __restrict__ bias, int N) {
    int v = (int)((blockIdx.x * blockDim.x + threadIdx.x) >> 5);
    int lane = threadIdx.x & 31;
    if (v >= N) return;
    int rs = g_rs[v];
    int dg = g_degcnt[v];
    const float2* __restrict__ hp2 = (const float2*)((EPI == 1) ? g_hp : g_out);
    float* __restrict__ dstbuf = (EPI == 1) ? g_out : g_hp;
    int half = lane >> 4;        // 0: even edges, 1: odd edges
    int hl   = lane & 15;        // feature pair index
    float ax = 0.f, ay = 0.f;

    for (int j0 = 0; j0 < dg; j0 += 32) {
        int jj = j0 + lane;
        int sv = (jj < dg) ? __ldg(&g_csrc[rs + jj]) : 0;
        int m = dg - j0; if (m > 32) m = 32;
        int kend = m & ~1;
        #pragma unroll 8
        for (int k = 0; k < 32; k += 2) {
            if (k >= kend) break;
            int s = __shfl_sync(0xffffffffu, sv, k + half);
            float2 f = __ldg(&hp2[(size_t)s * 16 + hl]);
            ax += f.x; ay += f.y;
        }
        if (m & 1) {             // odd tail: low half handles last edge
            int s = __shfl_sync(0xffffffffu, sv, m - 1);
            if (half == 0) {
                float2 f = __ldg(&hp2[(size_t)s * 16 + hl]);
                ax += f.x; ay += f.y;
            }
        }
    }
    // combine the two halves
    ax += __shfl_xor_sync(0xffffffffu, ax, 16);
    ay += __shfl_xor_sync(0xffffffffu, ay, 16);

    if (half == 0) {
        float2 f = __ldg(&hp2[(size_t)v * 16 + hl]);   // self loop
        ax += f.x; ay += f.y;
        float ds = rsqrtf((float)dg + 1.0f);
        float2 o;
        if (EPI == 1) {
            float2 bb = __ldg((const float2*)bias + hl);
            o.x = ds * fmaxf(ds * ax + bb.x, 0.f);
            o.y = ds * fmaxf(ds * ay + bb.y, 0.f);
        } else {
            o.x = ds * ax; o.y = ds * ay;
        }
        *(float2*)(dstbuf + (size_t)v * 32 + 2 * hl) = o;
    }
}

// -------- D=48 gather (R6 proven form), EPI=2 only --------
__global__ void __launch_bounds__(256)
gather48_kernel(int N) {
    int v = (int)((blockIdx.x * blockDim.x + threadIdx.x) >> 5);
    int lane = threadIdx.x & 31;
    if (v >= N) return;
    int rs = g_rs[v];
    int dg = g_degcnt[v];
    float a0 = 0.f, a1 = 0.f;
    const float* __restrict__ hp = g_out;

    for (int j0 = 0; j0 < dg; j0 += 32) {
        int jj = j0 + lane;
        int sv = (jj < dg) ? __ldg(&g_csrc[rs + jj]) : 0;
        int cnt = dg - j0; if (cnt > 32) cnt = 32;
        if (cnt == 32) {
            #pragma unroll 8
            for (int k = 0; k < 32; k++) {
                int s = __shfl_sync(0xffffffffu, sv, k);
                a0 += hp[(size_t)s * 48 + lane];
                if (lane < 16) a1 += hp[(size_t)s * 48 + 32 + lane];
            }
        } else {
            for (int k = 0; k < cnt; k++) {
                int s = __shfl_sync(0xffffffffu, sv, k);
                a0 += hp[(size_t)s * 48 + lane];
                if (lane < 16) a1 += hp[(size_t)s * 48 + 32 + lane];
            }
        }
    }
    a0 += hp[(size_t)v * 48 + lane];
    if (lane < 16) a1 += hp[(size_t)v * 48 + 32 + lane];
    float ds = rsqrtf((float)dg + 1.0f);
    g_hp[(size_t)v * 48 + lane] = ds * a0;
    if (lane < 16) g_hp[(size_t)v * 48 + 32 + lane] = ds * a1;
}

// -------- fused pool + MLP + softmax: one block per graph --------
__global__ void pool_mlp_kernel(const int* __restrict__ batch, int N,
                                const float* __restrict__ fc1w, const float* __restrict__ fc1b,
                                const float* __restrict__ fc2w, const float* __restrict__ fc2b,
                                float* __restrict__ out) {
    int g = blockIdx.x;
    int tid = threadIdx.x;
    __shared__ float sp[256];
    __shared__ float p[64];
    __shared__ float z[32];

    int lo = 0, hi = N;
    while (lo < hi) { int m = (lo + hi) >> 1; if (__ldg(&batch[m]) < g) lo = m + 1; else hi = m; }
    int start = lo;
    hi = N;
    while (lo < hi) { int m = (lo + hi) >> 1; if (__ldg(&batch[m]) < g + 1) lo = m + 1; else hi = m; }
    int end = lo;

    int c = tid & 63, part = tid >> 6;
    float acc = 0.f;
    for (int n = start + part; n < end; n += 4)
        acc += g_out[(size_t)n * 64 + c];
    sp[part * 64 + c] = acc;
    __syncthreads();
    if (tid < 64) {
        float invc = 1.0f / fmaxf((float)(end - start), 1.0f);
        p[tid] = (sp[tid] + sp[64 + tid] + sp[128 + tid] + sp[192 + tid]) * invc;
    }
    __syncthreads();
    if (tid < 32) {
        float a = fc1b[tid];
        #pragma unroll
        for (int i = 0; i < 64; i++) a += p[i] * fc1w[i * 32 + tid];
        z[tid] = fmaxf(a, 0.f);
        __syncwarp();
        if (tid < 16) {
            float l = fc2b[tid];
            #pragma unroll
            for (int j = 0; j < 32; j++) l += z[j] * fc2w[j * 16 + tid];
            float mx = l;
            #pragma unroll
            for (int o = 8; o; o >>= 1) mx = fmaxf(mx, __shfl_xor_sync(0xffffu, mx, o));
            float e = expf(l - mx);
            float s = e;
            #pragma unroll
            for (int o = 8; o; o >>= 1) s += __shfl_xor_sync(0xffffu, s, o);
            out[g * 16 + tid] = e / s;
        }
    }
}

extern "C" void kernel_launch(void* const* d_in, const int* in_sizes, int n_in,
                              void* d_out, int out_size) {
    const float* x     = (const float*)d_in[0];
    const int*   eidx  = (const int*)d_in[1];
    const int*   batch = (const int*)d_in[2];
    const float* W1 = (const float*)d_in[3];
    const float* b1 = (const float*)d_in[4];
    const float* W2 = (const float*)d_in[5];
    const float* b2 = (const float*)d_in[6];
    const float* W3 = (const float*)d_in[7];
    const float* b3 = (const float*)d_in[8];
    const float* fc1w = (const float*)d_in[9];
    const float* fc1b = (const float*)d_in[10];
    const float* fc2w = (const float*)d_in[11];
    const float* fc2b = (const float*)d_in[12];
    float* out = (float*)d_out;

    int N = in_sizes[0] / 128;
    int E = in_sizes[1] / 2;
    const int* src = eidx;
    const int* dst = eidx + E;

    cudaStream_t s2;
    cudaStreamCreateWithFlags(&s2, cudaStreamNonBlocking);
    cudaEvent_t evDeg, evG1;
    cudaEventCreateWithFlags(&evDeg, cudaEventDisableTiming);
    cudaEventCreateWithFlags(&evG1, cudaEventDisableTiming);

    void *p_deg, *p_scan;
    cudaGetSymbolAddress(&p_deg, g_degcnt);
    cudaGetSymbolAddress(&p_scan, g_scanstate);
    cudaMemsetAsync(p_deg, 0, (size_t)N * 4, 0);
    cudaMemsetAsync(p_scan, 0, (size_t)MAXSB * 8, 0);

    deg_kernel<<<(E + 255) / 256, 256>>>(dst, E);
    cudaEventRecord(evDeg, 0);

    // fork: gemm1 while CSR builds
    cudaStreamWaitEvent(s2, evDeg, 0);
    gemm_kernel<128, 32, 16, 0><<<(N + 15) / 16, 128, 0, s2>>>(x, W1, nullptr, N);
    cudaEventRecord(evG1, s2);

    int nb = (N + SCANB - 1) / SCANB;
    scan_kernel<<<nb, SCANB>>>(N);
    fill_csr_kernel<<<(E + 255) / 256, 256>>>(src, dst, E);

    cudaStreamWaitEvent(0, evG1, 0);

    int gth_blocks = (N + 7) / 8;
    int gemm_blocks = (N + 15) / 16;

    // L1: gather hp1(32) -> p1 in g_out
    gather32_kernel<1><<<gth_blocks, 256>>>(b1, N);
    // L2: gather p1(32) -> q2 in g_hp; gemm q2@W2 -> p2(48) in g_out
    gather32_kernel<2><<<gth_blocks, 256>>>(nullptr, N);
    gemm_kernel<32, 48, 16, 1><<<gemm_blocks, 192>>>(nullptr, W2, b2, N);
    // L3: gather p2(48) -> q3 in g_hp; gemm q3@W3 -> h3(64) in g_out
    gather48_kernel<<<gth_blocks, 256>>>(N);
    gemm_kernel<48, 64, 16, 2><<<gemm_blocks, 256>>>(nullptr, W3, b3, N);

    // fused pool + MLP + softmax
    pool_mlp_kernel<<<NGRAPH, 256>>>(batch, N, fc1w, fc1b, fc2w, fc2b, out);
}

// round 17
// speedup vs baseline: 1.3176x; 1.0151x over previous
#include <cuda_runtime.h>
#include <cuda_bf16.h>

#define MAXN 100000
#define MAXE 3200000
#define NGRAPH 512
#define DMAX 64
#define SCANB 512
#define MAXSB 512

// -------- device scratch --------
__device__ int   g_degcnt[MAXN];
__device__ int   g_rs    [MAXN];
__device__ int   g_cursor[MAXN];
__device__ unsigned long long g_scanstate[MAXSB];
__device__ int   g_csrc  [MAXE];
__device__ float g_hp    [MAXN * DMAX];   // buffer A
__device__ float g_out   [MAXN * DMAX];   // buffer B

// -------- degree (also zeroes scan state for this call, pre-scan) --------
__global__ void deg_kernel(const int* __restrict__ dst, int E) {
    int i = blockIdx.x * blockDim.x + threadIdx.x;
    if (i < MAXSB) g_scanstate[i] = 0ULL;   // replaces a memset launch
    if (i < E) atomicAdd(&g_degcnt[__ldg(&dst[i])], 1);
}

// -------- single-pass exclusive scan (decoupled lookback) --------
__global__ void scan_kernel(int N) {
    __shared__ int s[SCANB];
    __shared__ int s_prev;
    int t = threadIdx.x, b = blockIdx.x;
    int i = b * SCANB + t;
    int v = (i < N) ? g_degcnt[i] : 0;
    s[t] = v; __syncthreads();
    for (int o = 1; o < SCANB; o <<= 1) {
        int u = (t >= o) ? s[t - o] : 0;
        __syncthreads(); s[t] += u; __syncthreads();
    }
    int total = s[SCANB - 1];

    if (t == 0) {
        unsigned long long pkt = (b == 0)
            ? (((unsigned long long)2 << 32) | (unsigned)total)
            : (((unsigned long long)1 << 32) | (unsigned)total);
        __threadfence();
        atomicExch(&g_scanstate[b], pkt);
    }

    if (b > 0) {
        if (t < 32) {
            int prev = 0;
            int look = b - 1;
            while (true) {
                int idx = look - t;
                unsigned long long pkt;
                unsigned flag; int val;
                do {
                    pkt = (idx >= 0) ? atomicAdd(&g_scanstate[idx], 0ULL)
                                     : ((unsigned long long)2 << 32);
                    flag = (unsigned)(pkt >> 32);
                } while (__any_sync(0xffffffffu, flag == 0));
                val = (idx >= 0) ? (int)(unsigned)pkt : 0;
                unsigned pmask = __ballot_sync(0xffffffffu, flag == 2);
                if (pmask) {
                    int t2 = __ffs(pmask) - 1;
                    int contrib = (t <= t2) ? val : 0;
                    #pragma unroll
                    for (int o = 16; o; o >>= 1) contrib += __shfl_down_sync(0xffffffffu, contrib, o);
                    contrib = __shfl_sync(0xffffffffu, contrib, 0);
                    prev += contrib;
                    break;
                } else {
                    int contrib = val;
                    #pragma unroll
                    for (int o = 16; o; o >>= 1) contrib += __shfl_down_sync(0xffffffffu, contrib, o);
                    contrib = __shfl_sync(0xffffffffu, contrib, 0);
                    prev += contrib;
                    look -= 32;
                }
            }
            if (t == 0) {
                unsigned long long pkt = ((unsigned long long)2 << 32) | (unsigned)(prev + total);
                __threadfence();
                atomicExch(&g_scanstate[b], pkt);
                s_prev = prev;
            }
        }
        __syncthreads();
    } else {
        if (t == 0) s_prev = 0;
        __syncthreads();
    }
    int prev = s_prev;
    if (i < N) {
        int r = prev + s[t] - v;
        g_rs[i] = r;
        g_cursor[i] = r;
    }
}

// -------- CSR fill --------
__global__ void fill_csr_kernel(const int* __restrict__ src,
                                const int* __restrict__ dst, int E) {
    int i = blockIdx.x * blockDim.x + threadIdx.x;
    if (i < E) {
        int d = __ldg(&dst[i]);
        int p = atomicAdd(&g_cursor[d], 1);
        g_csrc[p] = __ldg(&src[i]);
    }
}

// -------- GEMM with fused epilogue --------
// EPI=0: src=Xext, dst=g_hp,  v = acc * dis
// EPI=1: src=g_hp, dst=g_out, v = relu(acc + b) * dis
// EPI=2: src=g_hp, dst=g_out, v = relu(acc + b)
template<int K, int M, int R, int EPI>
__global__ void gemm_kernel(const float* __restrict__ Xext,
                            const float* __restrict__ W,
                            const float* __restrict__ bias, int N) {
    constexpr int G = M / 4;
    __shared__ float4 sw[K * G];
    __shared__ float  sx[R * (K + 1)];
    const float* __restrict__ X = (EPI == 0) ? Xext : g_hp;
    float* __restrict__ DST = (EPI == 0) ? g_hp : g_out;
    int tid = threadIdx.x;
    const float4* W4 = (const float4*)W;
    for (int i = tid; i < K * G; i += blockDim.x) sw[i] = W4[i];
    int row0 = blockIdx.x * R;
    int nrows = N - row0; if (nrows > R) nrows = R;
    if (nrows <= 0) return;
    for (int i = tid; i < nrows * K; i += blockDim.x) {
        int r = i / K, k = i - r * K;
        sx[r * (K + 1) + k] = X[(size_t)(row0 + r) * K + k];
    }
    __syncthreads();
    int r = tid / G, g = tid - r * G;
    if (r < nrows) {
        float4 acc = {0.f, 0.f, 0.f, 0.f};
        const float* xr = &sx[r * (K + 1)];
        #pragma unroll 8
        for (int k = 0; k < K; k++) {
            float xv = xr[k];
            float4 wv = sw[k * G + g];
            acc.x += xv * wv.x; acc.y += xv * wv.y;
            acc.z += xv * wv.z; acc.w += xv * wv.w;
        }
        if (EPI == 0) {
            float ds = rsqrtf((float)g_degcnt[row0 + r] + 1.0f);
            acc.x *= ds; acc.y *= ds; acc.z *= ds; acc.w *= ds;
        } else {
            acc.x = fmaxf(acc.x + __ldg(&bias[4 * g]), 0.f);
            acc.y = fmaxf(acc.y + __ldg(&bias[4 * g + 1]), 0.f);
            acc.z = fmaxf(acc.z + __ldg(&bias[4 * g + 2]), 0.f);
            acc.w = fmaxf(acc.w + __ldg(&bias[4 * g + 3]), 0.f);
            if (EPI == 1) {
                float ds = rsqrtf((float)g_degcnt[row0 + r] + 1.0f);
                acc.x *= ds; acc.y *= ds; acc.z *= ds; acc.w *= ds;
            }
        }
        ((float4*)DST)[(size_t)(row0 + r) * G + g] = acc;
    }
}

// -------- D=32 paired-edge gather (R13 winner form) --------
template<int EPI>
__global__ void __launch_bounds__(256)
gather32_kernel(const float* __restrict__ bias, int N) {
    int v = (int)((blockIdx.x * blockDim.x + threadIdx.x) >> 5);
    int lane = threadIdx.x & 31;
    if (v >= N) return;
    int rs = g_rs[v];
    int dg = g_degcnt[v];
    const float2* __restrict__ hp2 = (const float2*)((EPI == 1) ? g_hp : g_out);
    float* __restrict__ dstbuf = (EPI == 1) ? g_out : g_hp;
    int half = lane >> 4;
    int hl   = lane & 15;
    float ax = 0.f, ay = 0.f;

    for (int j0 = 0; j0 < dg; j0 += 32) {
        int jj = j0 + lane;
        int sv = (jj < dg) ? __ldg(&g_csrc[rs + jj]) : 0;
        int m = dg - j0; if (m > 32) m = 32;
        int kend = m & ~1;
        #pragma unroll 8
        for (int k = 0; k < 32; k += 2) {
            if (k >= kend) break;
            int s = __shfl_sync(0xffffffffu, sv, k + half);
            float2 f = __ldg(&hp2[(size_t)s * 16 + hl]);
            ax += f.x; ay += f.y;
        }
        if (m & 1) {
            int s = __shfl_sync(0xffffffffu, sv, m - 1);
            if (half == 0) {
                float2 f = __ldg(&hp2[(size_t)s * 16 + hl]);
                ax += f.x; ay += f.y;
            }
        }
    }
    ax += __shfl_xor_sync(0xffffffffu, ax, 16);
    ay += __shfl_xor_sync(0xffffffffu, ay, 16);

    if (half == 0) {
        float2 f = __ldg(&hp2[(size_t)v * 16 + hl]);   // self loop
        ax += f.x; ay += f.y;
        float ds = rsqrtf((float)dg + 1.0f);
        float2 o;
        if (EPI == 1) {
            float2 bb = __ldg((const float2*)bias + hl);
            o.x = ds * fmaxf(ds * ax + bb.x, 0.f);
            o.y = ds * fmaxf(ds * ay + bb.y, 0.f);
        } else {
            o.x = ds * ax; o.y = ds * ay;
        }
        *(float2*)(dstbuf + (size_t)v * 32 + 2 * hl) = o;
    }
}

// -------- D=48 gather (R6 proven form), EPI=2 only --------
__global__ void __launch_bounds__(256)
gather48_kernel(int N) {
    int v = (int)((blockIdx.x * blockDim.x + threadIdx.x) >> 5);
    int lane = threadIdx.x & 31;
    if (v >= N) return;
    int rs = g_rs[v];
    int dg = g_degcnt[v];
    float a0 = 0.f, a1 = 0.f;
    const float* __restrict__ hp = g_out;

    for (int j0 = 0; j0 < dg; j0 += 32) {
        int jj = j0 + lane;
        int sv = (jj < dg) ? __ldg(&g_csrc[rs + jj]) : 0;
        int cnt = dg - j0; if (cnt > 32) cnt = 32;
        if (cnt == 32) {
            #pragma unroll 8
            for (int k = 0; k < 32; k++) {
                int s = __shfl_sync(0xffffffffu, sv, k);
                a0 += hp[(size_t)s * 48 + lane];
                if (lane < 16) a1 += hp[(size_t)s * 48 + 32 + lane];
            }
        } else {
            for (int k = 0; k < cnt; k++) {
                int s = __shfl_sync(0xffffffffu, sv, k);
                a0 += hp[(size_t)s * 48 + lane];
                if (lane < 16) a1 += hp[(size_t)s * 48 + 32 + lane];
            }
        }
    }
    a0 += hp[(size_t)v * 48 + lane];
    if (lane < 16) a1 += hp[(size_t)v * 48 + 32 + lane];
    float ds = rsqrtf((float)dg + 1.0f);
    g_hp[(size_t)v * 48 + lane] = ds * a0;
    if (lane < 16) g_hp[(size_t)v * 48 + 32 + lane] = ds * a1;
}

// -------- fused pool + MLP + softmax: one block per graph --------
__global__ void pool_mlp_kernel(const int* __restrict__ batch, int N,
                                const float* __restrict__ fc1w, const float* __restrict__ fc1b,
                                const float* __restrict__ fc2w, const float* __restrict__ fc2b,
                                float* __restrict__ out) {
    int g = blockIdx.x;
    int tid = threadIdx.x;
    __shared__ float sp[256];
    __shared__ float p[64];
    __shared__ float z[32];

    int lo = 0, hi = N;
    while (lo < hi) { int m = (lo + hi) >> 1; if (__ldg(&batch[m]) < g) lo = m + 1; else hi = m; }
    int start = lo;
    hi = N;
    while (lo < hi) { int m = (lo + hi) >> 1; if (__ldg(&batch[m]) < g + 1) lo = m + 1; else hi = m; }
    int end = lo;

    int c = tid & 63, part = tid >> 6;
    float acc = 0.f;
    for (int n = start + part; n < end; n += 4)
        acc += g_out[(size_t)n * 64 + c];
    sp[part * 64 + c] = acc;
    __syncthreads();
    if (tid < 64) {
        float invc = 1.0f / fmaxf((float)(end - start), 1.0f);
        p[tid] = (sp[tid] + sp[64 + tid] + sp[128 + tid] + sp[192 + tid]) * invc;
    }
    __syncthreads();
    if (tid < 32) {
        float a = fc1b[tid];
        #pragma unroll
        for (int i = 0; i < 64; i++) a += p[i] * fc1w[i * 32 + tid];
        z[tid] = fmaxf(a, 0.f);
        __syncwarp();
        if (tid < 16) {
            float l = fc2b[tid];
            #pragma unroll
            for (int j = 0; j < 32; j++) l += z[j] * fc2w[j * 16 + tid];
            float mx = l;
            #pragma unroll
            for (int o = 8; o; o >>= 1) mx = fmaxf(mx, __shfl_xor_sync(0xffffu, mx, o));
            float e = expf(l - mx);
            float s = e;
            #pragma unroll
            for (int o = 8; o; o >>= 1) s += __shfl_xor_sync(0xffffu, s, o);
            out[g * 16 + tid] = e / s;
        }
    }
}

extern "C" void kernel_launch(void* const* d_in, const int* in_sizes, int n_in,
                              void* d_out, int out_size) {
    const float* x     = (const float*)d_in[0];
    const int*   eidx  = (const int*)d_in[1];
    const int*   batch = (const int*)d_in[2];
    const float* W1 = (const float*)d_in[3];
    const float* b1 = (const float*)d_in[4];
    const float* W2 = (const float*)d_in[5];
    const float* b2 = (const float*)d_in[6];
    const float* W3 = (const float*)d_in[7];
    const float* b3 = (const float*)d_in[8];
    const float* fc1w = (const float*)d_in[9];
    const float* fc1b = (const float*)d_in[10];
    const float* fc2w = (const float*)d_in[11];
    const float* fc2b = (const float*)d_in[12];
    float* out = (float*)d_out;

    int N = in_sizes[0] / 128;
    int E = in_sizes[1] / 2;
    const int* src = eidx;
    const int* dst = eidx + E;

    cudaStream_t s2;
    cudaStreamCreateWithFlags(&s2, cudaStreamNonBlocking);
    cudaEvent_t evDeg, evG1;
    cudaEventCreateWithFlags(&evDeg, cudaEventDisableTiming);
    cudaEventCreateWithFlags(&evG1, cudaEventDisableTiming);

    void *p_deg;
    cudaGetSymbolAddress(&p_deg, g_degcnt);
    cudaMemsetAsync(p_deg, 0, (size_t)N * 4, 0);   // only remaining memset

    deg_kernel<<<(E + 255) / 256, 256>>>(dst, E);  // also zeroes g_scanstate
    cudaEventRecord(evDeg, 0);

    // fork: gemm1 while CSR builds
    cudaStreamWaitEvent(s2, evDeg, 0);
    gemm_kernel<128, 32, 16, 0><<<(N + 15) / 16, 128, 0, s2>>>(x, W1, nullptr, N);
    cudaEventRecord(evG1, s2);

    int nb = (N + SCANB - 1) / SCANB;
    scan_kernel<<<nb, SCANB>>>(N);
    fill_csr_kernel<<<(E + 255) / 256, 256>>>(src, dst, E);

    cudaStreamWaitEvent(0, evG1, 0);

    int gth_blocks = (N + 7) / 8;
    int gemm_blocks = (N + 15) / 16;

    // L1: gather hp1(32) -> p1 in g_out    [6th launch -> ncu window]
    gather32_kernel<1><<<gth_blocks, 256>>>(b1, N);
    // L2: gather p1(32) -> q2 in g_hp; gemm q2@W2 -> p2(48) in g_out
    gather32_kernel<2><<<gth_blocks, 256>>>(nullptr, N);
    gemm_kernel<32, 48, 16, 1><<<gemm_blocks, 192>>>(nullptr, W2, b2, N);
    // L3: gather p2(48) -> q3 in g_hp; gemm q3@W3 -> h3(64) in g_out
    gather48_kernel<<<gth_blocks, 256>>>(N);
    gemm_kernel<48, 64, 16, 2><<<gemm_blocks, 256>>>(nullptr, W3, b3, N);

    // fused pool + MLP + softmax
    pool_mlp_kernel<<<NGRAPH, 256>>>(batch, N, fc1w, fc1b, fc2w, fc2b, out);
}